// round 5
// baseline (speedup 1.0000x reference)
#include <cuda_runtime.h>
#include <cstdint>
#include <cstddef>

#define BB 4
#define SS 2048
#define EE 1024
#define DD 64
#define HH 16

// ---------------- scratch (static __device__ globals: allocation-free) -------------
__device__ float g_Qhi[BB * SS * DD];                 // [b][s][d] tf32-hi
__device__ float g_Qlo[BB * SS * DD];
__device__ float g_Khi[BB * SS * DD];
__device__ float g_Klo[BB * SS * DD];
__device__ float g_V  [BB * SS * DD];                 // [b][k][d] fp32
__device__ float g_Wvh[BB * DD * SS];                 // [b][d][k] = (V^T * 1/Z) hi
__device__ float g_Wvl[BB * DD * SS];                 // lo
__device__ float g_Ehi[(size_t)BB * SS * SS];         // [b][i][j] exp(S) tf32-hi  (64 MB)
__device__ float g_Elo[(size_t)BB * SS * SS];         // lo                        (64 MB)
__device__ float g_Zpart[BB * 16 * SS];
__device__ float g_Zinv[BB * SS];
__device__ float g_Opart[BB * 8 * SS * DD];           // k-split partial outputs (16 MB)

// ---------------- helpers ----------------------------------------------------------
// cvt.rna.tf32.f32 writes a .b32 destination (fp32 bit pattern, mantissa truncated).
__device__ __forceinline__ void tf32split(float a, float& hi, float& lo) {
    uint32_t h, l;
    asm("cvt.rna.tf32.f32 %0, %1;" : "=r"(h) : "f"(a));
    hi = __uint_as_float(h);
    float r = a - hi;
    asm("cvt.rna.tf32.f32 %0, %1;" : "=r"(l) : "f"(r));
    lo = __uint_as_float(l);
}

// m16n8k8 tf32 warp MMA (portable sm_80+ path; compiles at target sm_100)
__device__ __forceinline__ void mma168(float* c, const uint32_t* a, const uint32_t* b) {
    asm volatile(
        "mma.sync.aligned.m16n8k8.row.col.f32.tf32.tf32.f32 "
        "{%0,%1,%2,%3}, {%4,%5,%6,%7}, {%8,%9}, {%0,%1,%2,%3};"
        : "+f"(c[0]), "+f"(c[1]), "+f"(c[2]), "+f"(c[3])
        : "r"(a[0]), "r"(a[1]), "r"(a[2]), "r"(a[3]), "r"(b[0]), "r"(b[1]));
}

#define PITCH 68   // smem tile pitch (floats): 16B-aligned rows, conflict-free frag loads

// load rows x 64 fp32 tile (gmem pitch pitch_f) into smem pitch-68 tile; 256 threads
__device__ __forceinline__ void ldt(float* dst, const float* __restrict__ src,
                                    int rows, int pitch_f) {
    for (int idx = threadIdx.x; idx < rows * 16; idx += 256) {
        int r = idx >> 4, c4 = (idx & 15) << 2;
        float4 v = *(const float4*)(src + (size_t)r * pitch_f + c4);
        *(float4*)(dst + r * PITCH + c4) = v;
    }
}

// =====================================================================================
// Kernel 1: projections (SIMT fp32). Q,K -> tf32 hi/lo row-major; V fp32.
// =====================================================================================
__global__ __launch_bounds__(256) void proj_kernel(const float* __restrict__ x,
                                                   const float* __restrict__ Wq,
                                                   const float* __restrict__ Wk,
                                                   const float* __restrict__ Wv) {
    __shared__ float As[16][76];
    __shared__ float Bs[16][64];

    const int z  = blockIdx.y;
    const float* __restrict__ W = (z == 0) ? Wq : (z == 1) ? Wk : Wv;
    const int m0 = blockIdx.x * 64;
    const int t  = threadIdx.x;
    const int tx = t & 15;
    const int ty = t >> 4;

    const int xi = t >> 2;
    const int xk = (t & 3) << 2;
    const int wk = t >> 4;
    const int wn = (t & 15) << 2;

    float acc[4][4] = {};

    for (int k0 = 0; k0 < EE; k0 += 16) {
        float4 av = *(const float4*)(x + (size_t)(m0 + xi) * EE + k0 + xk);
        float4 bv = *(const float4*)(W + (size_t)(k0 + wk) * DD + wn);
        As[xk + 0][xi] = av.x;
        As[xk + 1][xi] = av.y;
        As[xk + 2][xi] = av.z;
        As[xk + 3][xi] = av.w;
        *(float4*)(&Bs[wk][wn]) = bv;
        __syncthreads();

        #pragma unroll
        for (int kk = 0; kk < 16; kk++) {
            float4 a4 = *(const float4*)(&As[kk][ty * 4]);
            float4 b4 = *(const float4*)(&Bs[kk][tx * 4]);
            float a[4] = {a4.x, a4.y, a4.z, a4.w};
            float b[4] = {b4.x, b4.y, b4.z, b4.w};
            #pragma unroll
            for (int r = 0; r < 4; r++)
                #pragma unroll
                for (int c = 0; c < 4; c++)
                    acc[r][c] += a[r] * b[c];
        }
        __syncthreads();
    }

    if (z == 2) {
        #pragma unroll
        for (int r = 0; r < 4; r++) {
            int m = m0 + ty * 4 + r;
            int b = m >> 11, s = m & 2047;
            float4 v = make_float4(acc[r][0], acc[r][1], acc[r][2], acc[r][3]);
            *(float4*)(g_V + ((size_t)(b * SS + s)) * DD + tx * 4) = v;
        }
    } else {
        float* __restrict__ dh = z ? g_Khi : g_Qhi;
        float* __restrict__ dl = z ? g_Klo : g_Qlo;
        #pragma unroll
        for (int r = 0; r < 4; r++) {
            int m = m0 + ty * 4 + r;
            int b = m >> 11, s = m & 2047;
            float h[4], l[4];
            #pragma unroll
            for (int e = 0; e < 4; e++) tf32split(acc[r][e], h[e], l[e]);
            size_t off = ((size_t)(b * SS + s)) * DD + tx * 4;
            *(float4*)(dh + off) = make_float4(h[0], h[1], h[2], h[3]);
            *(float4*)(dl + off) = make_float4(l[0], l[1], l[2], l[3]);
        }
    }
}

// =====================================================================================
// Kernel 2 (score): 128x128 S-tile via 3xTF32 mma.sync, exp, store E hi/lo,
// column partial sums -> Zpart. grid (16 i, 16 j, 4 b), 256 threads (8 warps, 4x2).
// =====================================================================================
#define SC_QH 0
#define SC_QL 34816
#define SC_KH 69632
#define SC_KL 104448
#define SC_RED 139264                 // [256][17] floats
#define SMEM_SC (139264 + 17408)

__global__ __launch_bounds__(256) void score_kernel() {
    extern __shared__ float sm[];
    const int tid  = threadIdx.x;
    const int lane = tid & 31, warp = tid >> 5;
    const int wi = warp >> 1, wj = warp & 1;
    const int r = lane >> 2, c = lane & 3;
    const int b = blockIdx.z, i0 = blockIdx.x * 128, j0 = blockIdx.y * 128;

    float* Qh = sm + (SC_QH >> 2);
    float* Ql = sm + (SC_QL >> 2);
    float* Kh = sm + (SC_KH >> 2);
    float* Kl = sm + (SC_KL >> 2);
    float* red = sm + (SC_RED >> 2);

    ldt(Qh, g_Qhi + (size_t)(b * SS + i0) * DD, 128, DD);
    ldt(Ql, g_Qlo + (size_t)(b * SS + i0) * DD, 128, DD);
    ldt(Kh, g_Khi + (size_t)(b * SS + j0) * DD, 128, DD);
    ldt(Kl, g_Klo + (size_t)(b * SS + j0) * DD, 128, DD);
    __syncthreads();

    float C[2][8][4] = {};

    #pragma unroll
    for (int s3 = 0; s3 < 3; s3++) {
        const float* A  = (s3 == 2) ? Ql : Qh;
        const float* Bm = (s3 == 1) ? Kl : Kh;
        #pragma unroll
        for (int ks = 0; ks < 8; ks++) {
            const int k0 = ks * 8;
            uint32_t a[2][4], bf[8][2];
            #pragma unroll
            for (int mt = 0; mt < 2; mt++) {
                int row = wi * 32 + mt * 16 + r;
                a[mt][0] = __float_as_uint(A[row * PITCH + k0 + c]);
                a[mt][1] = __float_as_uint(A[(row + 8) * PITCH + k0 + c]);
                a[mt][2] = __float_as_uint(A[row * PITCH + k0 + c + 4]);
                a[mt][3] = __float_as_uint(A[(row + 8) * PITCH + k0 + c + 4]);
            }
            #pragma unroll
            for (int nt = 0; nt < 8; nt++) {
                int jr = wj * 64 + nt * 8 + r;
                bf[nt][0] = __float_as_uint(Bm[jr * PITCH + k0 + c]);
                bf[nt][1] = __float_as_uint(Bm[jr * PITCH + k0 + c + 4]);
            }
            #pragma unroll
            for (int mt = 0; mt < 2; mt++)
                #pragma unroll
                for (int nt = 0; nt < 8; nt++)
                    mma168(C[mt][nt], a[mt], bf[nt]);
        }
    }

    // exp, split, store E, accumulate column partials
    float part[16];
    #pragma unroll
    for (int p = 0; p < 16; p++) part[p] = 0.f;

    #pragma unroll
    for (int mt = 0; mt < 2; mt++) {
        #pragma unroll
        for (int nt = 0; nt < 8; nt++) {
            float e0 = __expf(C[mt][nt][0]);
            float e1 = __expf(C[mt][nt][1]);
            float e2 = __expf(C[mt][nt][2]);
            float e3 = __expf(C[mt][nt][3]);
            int ig = i0 + wi * 32 + mt * 16 + r;
            int jg = j0 + wj * 64 + nt * 8 + 2 * c;
            float h0, l0, h1, l1, h2, l2, h3, l3;
            tf32split(e0, h0, l0); tf32split(e1, h1, l1);
            tf32split(e2, h2, l2); tf32split(e3, h3, l3);
            size_t b0 = ((size_t)b * SS + ig) * SS + jg;
            size_t b1 = ((size_t)b * SS + ig + 8) * SS + jg;
            *(float2*)(g_Ehi + b0) = make_float2(h0, h1);
            *(float2*)(g_Elo + b0) = make_float2(l0, l1);
            *(float2*)(g_Ehi + b1) = make_float2(h2, h3);
            *(float2*)(g_Elo + b1) = make_float2(l2, l3);
            part[nt * 2 + 0] += e0 + e2;
            part[nt * 2 + 1] += e1 + e3;
        }
    }
    #pragma unroll
    for (int p = 0; p < 16; p++) red[tid * 17 + p] = part[p];
    __syncthreads();

    if (tid < 128) {
        int t_wj = tid >> 6, jl = tid & 63;
        int nt = jl >> 3, cc = (jl & 7) >> 1, par = jl & 1;
        int p = nt * 2 + par;
        float s = 0.f;
        #pragma unroll
        for (int twi = 0; twi < 4; twi++)
            #pragma unroll
            for (int q = 0; q < 8; q++)
                s += red[((twi * 2 + t_wj) * 32 + q * 4 + cc) * 17 + p];
        g_Zpart[((size_t)(b * 16 + blockIdx.x)) * SS + j0 + tid] = s;
    }
}

// =====================================================================================
// Kernel 3/4: Z reduce ; V^T/Z transpose + split.
// =====================================================================================
__global__ void zinv_kernel() {
    int t = blockIdx.x * 256 + threadIdx.x;
    int b = t >> 11, j = t & 2047;
    float s = 0.f;
    #pragma unroll
    for (int p = 0; p < 16; p++) s += g_Zpart[((size_t)(b * 16 + p)) * SS + j];
    g_Zinv[t] = 1.0f / s;
}

__global__ __launch_bounds__(256) void vscale_kernel() {
    __shared__ float vs[64][65];
    const int b = blockIdx.y, k0 = blockIdx.x * 64, t = threadIdx.x;
    for (int idx = t; idx < 1024; idx += 256) {
        int r = idx >> 4, c4 = (idx & 15) << 2;
        float zi = g_Zinv[b * SS + k0 + r];
        float4 v = *(const float4*)(g_V + ((size_t)(b * SS + k0 + r)) * DD + c4);
        vs[r][c4 + 0] = v.x * zi; vs[r][c4 + 1] = v.y * zi;
        vs[r][c4 + 2] = v.z * zi; vs[r][c4 + 3] = v.w * zi;
    }
    __syncthreads();
    for (int idx = t; idx < 1024; idx += 256) {
        int d = idx >> 4, c4 = (idx & 15) << 2;
        float h[4], l[4];
        #pragma unroll
        for (int e = 0; e < 4; e++) tf32split(vs[c4 + e][d], h[e], l[e]);
        size_t off = ((size_t)(b * DD + d)) * SS + k0 + c4;
        *(float4*)(g_Wvh + off) = make_float4(h[0], h[1], h[2], h[3]);
        *(float4*)(g_Wvl + off) = make_float4(l[0], l[1], l[2], l[3]);
    }
}

// =====================================================================================
// Kernel 5 (out): partial out = E[i, k-chunk] @ Wv^T, 3xTF32 mma.sync.
// grid (16 i, 8 ksplit, 4 b), 256 threads (8 warps, 4x2 over M=128,N=64).
// =====================================================================================
#define OU_EH 0
#define OU_EL 34816
#define OU_WH 69632
#define OU_WL 87040
#define SMEM_OU (87040 + 17408)

__global__ __launch_bounds__(256) void out_kernel() {
    extern __shared__ float sm[];
    const int tid  = threadIdx.x;
    const int lane = tid & 31, warp = tid >> 5;
    const int wi = warp >> 1, wj = warp & 1;
    const int r = lane >> 2, c = lane & 3;
    const int b = blockIdx.z, i0 = blockIdx.x * 128, ks_id = blockIdx.y;

    float* Eh = sm + (OU_EH >> 2);
    float* El = sm + (OU_EL >> 2);
    float* Wh = sm + (OU_WH >> 2);
    float* Wl = sm + (OU_WL >> 2);

    float C[2][4][4] = {};

    for (int kc = 0; kc < 4; kc++) {
        const int k0 = ks_id * 256 + kc * 64;
        ldt(Eh, g_Ehi + ((size_t)b * SS + i0) * SS + k0, 128, SS);
        ldt(El, g_Elo + ((size_t)b * SS + i0) * SS + k0, 128, SS);
        ldt(Wh, g_Wvh + (size_t)b * DD * SS + k0, 64, SS);
        ldt(Wl, g_Wvl + (size_t)b * DD * SS + k0, 64, SS);
        __syncthreads();

        #pragma unroll
        for (int s3 = 0; s3 < 3; s3++) {
            const float* A  = (s3 == 2) ? El : Eh;
            const float* Bm = (s3 == 1) ? Wl : Wh;
            #pragma unroll
            for (int ks = 0; ks < 8; ks++) {
                const int kk = ks * 8;
                uint32_t a[2][4], bf[4][2];
                #pragma unroll
                for (int mt = 0; mt < 2; mt++) {
                    int row = wi * 32 + mt * 16 + r;
                    a[mt][0] = __float_as_uint(A[row * PITCH + kk + c]);
                    a[mt][1] = __float_as_uint(A[(row + 8) * PITCH + kk + c]);
                    a[mt][2] = __float_as_uint(A[row * PITCH + kk + c + 4]);
                    a[mt][3] = __float_as_uint(A[(row + 8) * PITCH + kk + c + 4]);
                }
                #pragma unroll
                for (int nt = 0; nt < 4; nt++) {
                    int dr = wj * 32 + nt * 8 + r;
                    bf[nt][0] = __float_as_uint(Bm[dr * PITCH + kk + c]);
                    bf[nt][1] = __float_as_uint(Bm[dr * PITCH + kk + c + 4]);
                }
                #pragma unroll
                for (int mt = 0; mt < 2; mt++)
                    #pragma unroll
                    for (int nt = 0; nt < 4; nt++)
                        mma168(C[mt][nt], a[mt], bf[nt]);
            }
        }
        __syncthreads();
    }

    // store partial
    #pragma unroll
    for (int mt = 0; mt < 2; mt++) {
        #pragma unroll
        for (int nt = 0; nt < 4; nt++) {
            int ig = i0 + wi * 32 + mt * 16 + r;
            int dg = wj * 32 + nt * 8 + 2 * c;
            size_t base = ((size_t)((b * 8 + ks_id) * SS + ig)) * DD + dg;
            *(float2*)(g_Opart + base) = make_float2(C[mt][nt][0], C[mt][nt][1]);
            *(float2*)(g_Opart + base + 8 * DD) = make_float2(C[mt][nt][2], C[mt][nt][3]);
        }
    }
}

// =====================================================================================
// Kernel 6: reduce 8 k-split partials, write 16 tiled head copies.
// =====================================================================================
__global__ void finalize_kernel(float* __restrict__ out) {
    int g = blockIdx.x * 256 + threadIdx.x;     // 0 .. BB*SS*16-1
    int c4 = (g & 15) << 2;
    int i  = (g >> 4) & 2047;
    int b  = g >> 15;
    float4 s = make_float4(0.f, 0.f, 0.f, 0.f);
    #pragma unroll
    for (int sp = 0; sp < 8; sp++) {
        float4 p = *(const float4*)(g_Opart + ((size_t)((b * 8 + sp) * SS + i)) * DD + c4);
        s.x += p.x; s.y += p.y; s.z += p.z; s.w += p.w;
    }
    float* base = out + ((size_t)(b * SS + i)) * (HH * DD) + c4;
    #pragma unroll
    for (int h = 0; h < HH; h++) *(float4*)(base + h * DD) = s;
}

// =====================================================================================
extern "C" void kernel_launch(void* const* d_in, const int* in_sizes, int n_in,
                              void* d_out, int out_size) {
    const float* x  = (const float*)d_in[0];
    const float* Wq = (const float*)d_in[1];
    const float* Wk = (const float*)d_in[2];
    const float* Wv = (const float*)d_in[3];
    float* out = (float*)d_out;

    cudaFuncSetAttribute(score_kernel, cudaFuncAttributeMaxDynamicSharedMemorySize, SMEM_SC);
    cudaFuncSetAttribute(out_kernel,   cudaFuncAttributeMaxDynamicSharedMemorySize, SMEM_OU);

    proj_kernel<<<dim3(BB * SS / 64, 3), 256>>>(x, Wq, Wk, Wv);
    score_kernel<<<dim3(16, 16, BB), 256, SMEM_SC>>>();
    zinv_kernel<<<(BB * SS) / 256, 256>>>();
    vscale_kernel<<<dim3(SS / 64, BB), 256>>>();
    out_kernel<<<dim3(16, 8, BB), 256, SMEM_OU>>>();
    finalize_kernel<<<(BB * SS * 16) / 256, 256>>>(out);
}

// round 6
// speedup vs baseline: 2.5387x; 2.5387x over previous
#include <cuda_runtime.h>
#include <cuda_bf16.h>
#include <cstdint>
#include <cstddef>

#define BB 4
#define SS 2048
#define EE 1024
#define DD 64
#define HH 16

// ---------------- scratch (static __device__ globals: allocation-free) -------------
__device__ __align__(16) float    g_Q[BB * SS * DD];        // fp32 projections
__device__ __align__(16) float    g_K[BB * SS * DD];
__device__ __align__(16) float    g_V[BB * SS * DD];
__device__ __align__(16) uint32_t g_Wth[192 * 512];         // W^T bf16x2-hi [n=192][k-pairs=512]
__device__ __align__(16) uint32_t g_Wtl[192 * 512];         // lo
__device__ __align__(16) float    g_E[(size_t)BB * SS * SS];// exp(S) fp32 (64 MB)
__device__ __align__(16) float    g_Wvt[BB * DD * SS];      // (V^T * 1/Z) tf32-rounded [b][d][k]
__device__ __align__(16) float    g_Zpart[BB * 16 * SS];
__device__ __align__(16) float    g_Zinv[BB * SS];
__device__ __align__(16) float    g_Opart[BB * 8 * SS * DD];

// ---------------- helpers ----------------------------------------------------------
__device__ __forceinline__ float tf32rna(float a) {
    uint32_t r;
    asm("cvt.rna.tf32.f32 %0, %1;" : "=r"(r) : "f"(a));
    return __uint_as_float(r);
}

// bf16 2-way split of two floats, packed as bf16x2 (low half = first element)
__device__ __forceinline__ void split2(float a, float b, uint32_t& hi, uint32_t& lo) {
    __nv_bfloat162 H, L;
    H.x = __float2bfloat16_rn(a);
    H.y = __float2bfloat16_rn(b);
    L.x = __float2bfloat16_rn(a - __bfloat162float(H.x));
    L.y = __float2bfloat16_rn(b - __bfloat162float(H.y));
    hi = *(uint32_t*)&H;
    lo = *(uint32_t*)&L;
}

// m16n8k16 bf16 warp MMA (fp32 accum)
__device__ __forceinline__ void mma_bf16(float* c, const uint32_t* a, const uint32_t* b) {
    asm volatile(
        "mma.sync.aligned.m16n8k16.row.col.f32.bf16.bf16.f32 "
        "{%0,%1,%2,%3}, {%4,%5,%6,%7}, {%8,%9}, {%0,%1,%2,%3};"
        : "+f"(c[0]), "+f"(c[1]), "+f"(c[2]), "+f"(c[3])
        : "r"(a[0]), "r"(a[1]), "r"(a[2]), "r"(a[3]), "r"(b[0]), "r"(b[1]));
}

// m16n8k8 tf32 warp MMA
__device__ __forceinline__ void mma168(float* c, const uint32_t* a, const uint32_t* b) {
    asm volatile(
        "mma.sync.aligned.m16n8k8.row.col.f32.tf32.tf32.f32 "
        "{%0,%1,%2,%3}, {%4,%5,%6,%7}, {%8,%9}, {%0,%1,%2,%3};"
        : "+f"(c[0]), "+f"(c[1]), "+f"(c[2]), "+f"(c[3])
        : "r"(a[0]), "r"(a[1]), "r"(a[2]), "r"(a[3]), "r"(b[0]), "r"(b[1]));
}

#define PITCH 68    // fp32 smem tile pitch (out kernel)
#define UPITCH 36   // u32 (bf16x2) smem tile pitch: row*36 mod 32 = row*4 -> conflict-free frags

// fp32 tile load (256 threads), optional tf32 rounding
__device__ __forceinline__ void ldt(float* dst, const float* __restrict__ src,
                                    int rows, int pitch_f) {
    for (int idx = threadIdx.x; idx < rows * 16; idx += 256) {
        int r = idx >> 4, c4 = (idx & 15) << 2;
        float4 v = *(const float4*)(src + (size_t)r * pitch_f + c4);
        *(float4*)(dst + r * PITCH + c4) = v;
    }
}
__device__ __forceinline__ void ldt_cvt(float* dst, const float* __restrict__ src,
                                        int rows, int pitch_f) {
    for (int idx = threadIdx.x; idx < rows * 16; idx += 256) {
        int r = idx >> 4, c4 = (idx & 15) << 2;
        float4 v = *(const float4*)(src + (size_t)r * pitch_f + c4);
        v.x = tf32rna(v.x); v.y = tf32rna(v.y); v.z = tf32rna(v.z); v.w = tf32rna(v.w);
        *(float4*)(dst + r * PITCH + c4) = v;
    }
}

// =====================================================================================
// Kernel 0: pre-split W^T into bf16 hi/lo [n=192][k=1024] (pairs along k).
// =====================================================================================
__global__ void wsplit_kernel(const float* __restrict__ Wq,
                              const float* __restrict__ Wk,
                              const float* __restrict__ Wv) {
    int n = blockIdx.x;                 // 0..191
    int z = n >> 6, d = n & 63;
    const float* __restrict__ W = (z == 0) ? Wq : (z == 1) ? Wk : Wv;
    for (int k2 = threadIdx.x; k2 < 512; k2 += 256) {
        float a = W[(size_t)(2 * k2) * DD + d];
        float b = W[(size_t)(2 * k2 + 1) * DD + d];
        uint32_t hi, lo;
        split2(a, b, hi, lo);
        g_Wth[n * 512 + k2] = hi;
        g_Wtl[n * 512 + k2] = lo;
    }
}

// =====================================================================================
// Kernel 1: projections via bf16x2 3-term mma.sync. grid (128 mtiles, 3 z), 128 thr.
// M=64, N=64, K=1024 (chunks of 64). Outputs fp32 Q/K/V.
// =====================================================================================
__global__ __launch_bounds__(128) void projmma_kernel(const float* __restrict__ x) {
    __shared__ uint32_t smu[4 * 64 * UPITCH];     // Xh, Xl, Wh, Wl  (36864 B)
    uint32_t* Xh = smu;
    uint32_t* Xl = Xh + 64 * UPITCH;
    uint32_t* Wh = Xl + 64 * UPITCH;
    uint32_t* Wl = Wh + 64 * UPITCH;

    const int z  = blockIdx.y;
    const int m0 = blockIdx.x * 64;
    const int tid = threadIdx.x, lane = tid & 31, warp = tid >> 5;
    const int wi = warp >> 1, wj = warp & 1;
    const int g = lane >> 2, c = lane & 3;

    float C[2][4][4] = {};

    for (int k0 = 0; k0 < EE; k0 += 64) {
        // x tile 64x64: load fp32, split, pack
        for (int idx = tid; idx < 1024; idx += 128) {
            int r = idx >> 4, c4 = (idx & 15) << 2;
            float4 v = *(const float4*)(x + (size_t)(m0 + r) * EE + k0 + c4);
            uint32_t h0, l0, h1, l1;
            split2(v.x, v.y, h0, l0);
            split2(v.z, v.w, h1, l1);
            int base = r * UPITCH + (c4 >> 1);
            Xh[base] = h0; Xh[base + 1] = h1;
            Xl[base] = l0; Xl[base + 1] = l1;
        }
        // W^T tile 64x64 (pre-split): plain uint4 copies
        for (int idx = tid; idx < 512; idx += 128) {
            int r = idx >> 3, c16 = (idx & 7) << 2;
            size_t off = (size_t)(z * 64 + r) * 512 + (k0 >> 1) + c16;
            *(uint4*)(Wh + r * UPITCH + c16) = *(const uint4*)(g_Wth + off);
            *(uint4*)(Wl + r * UPITCH + c16) = *(const uint4*)(g_Wtl + off);
        }
        __syncthreads();

        #pragma unroll
        for (int t3 = 0; t3 < 3; t3++) {
            const uint32_t* A = (t3 == 2) ? Xl : Xh;
            const uint32_t* B = (t3 == 1) ? Wl : Wh;
            #pragma unroll
            for (int ks = 0; ks < 4; ks++) {
                int kb = ks * 8;
                uint32_t a[2][4], bb[4][2];
                #pragma unroll
                for (int mt = 0; mt < 2; mt++) {
                    int row = wi * 32 + mt * 16 + g;
                    a[mt][0] = A[row * UPITCH + kb + c];
                    a[mt][1] = A[(row + 8) * UPITCH + kb + c];
                    a[mt][2] = A[row * UPITCH + kb + c + 4];
                    a[mt][3] = A[(row + 8) * UPITCH + kb + c + 4];
                }
                #pragma unroll
                for (int nt = 0; nt < 4; nt++) {
                    int n = wj * 32 + nt * 8 + g;
                    bb[nt][0] = B[n * UPITCH + kb + c];
                    bb[nt][1] = B[n * UPITCH + kb + c + 4];
                }
                #pragma unroll
                for (int mt = 0; mt < 2; mt++)
                    #pragma unroll
                    for (int nt = 0; nt < 4; nt++)
                        mma_bf16(C[mt][nt], a[mt], bb[nt]);
            }
        }
        __syncthreads();
    }

    float* __restrict__ dst = (z == 0) ? g_Q : (z == 1) ? g_K : g_V;
    #pragma unroll
    for (int mt = 0; mt < 2; mt++)
        #pragma unroll
        for (int nt = 0; nt < 4; nt++) {
            int m = m0 + wi * 32 + mt * 16 + g;
            int col = wj * 32 + nt * 8 + 2 * c;
            *(float2*)(dst + (size_t)m * DD + col) = make_float2(C[mt][nt][0], C[mt][nt][1]);
            *(float2*)(dst + (size_t)(m + 8) * DD + col) = make_float2(C[mt][nt][2], C[mt][nt][3]);
        }
}

// =====================================================================================
// Kernel 2 (score): 128x128 S-tile via bf16x2 3-term mma.sync, exp, store E fp32,
// column partial sums -> Zpart. grid (16 i, 16 j, 4 b), 256 threads (8 warps 4x2).
// =====================================================================================
#define SC_SMEM (4 * 128 * UPITCH * 4 + 256 * 17 * 4)   // 73728 + 17408 = 91136

__global__ __launch_bounds__(256) void score_kernel() {
    extern __shared__ uint32_t smu[];
    uint32_t* Qh = smu;
    uint32_t* Ql = Qh + 128 * UPITCH;
    uint32_t* Kh = Ql + 128 * UPITCH;
    uint32_t* Kl = Kh + 128 * UPITCH;
    float* red = (float*)(Kl + 128 * UPITCH);

    const int tid = threadIdx.x, lane = tid & 31, warp = tid >> 5;
    const int wi = warp >> 1, wj = warp & 1;
    const int g = lane >> 2, c = lane & 3;
    const int b = blockIdx.z, i0 = blockIdx.x * 128, j0 = blockIdx.y * 128;

    for (int idx = tid; idx < 2048; idx += 256) {
        int r = idx >> 4, c4 = (idx & 15) << 2;
        int base = r * UPITCH + (c4 >> 1);
        uint32_t h0, l0, h1, l1;
        float4 v = *(const float4*)(g_Q + (size_t)(b * SS + i0 + r) * DD + c4);
        split2(v.x, v.y, h0, l0);
        split2(v.z, v.w, h1, l1);
        Qh[base] = h0; Qh[base + 1] = h1;
        Ql[base] = l0; Ql[base + 1] = l1;
        float4 w = *(const float4*)(g_K + (size_t)(b * SS + j0 + r) * DD + c4);
        split2(w.x, w.y, h0, l0);
        split2(w.z, w.w, h1, l1);
        Kh[base] = h0; Kh[base + 1] = h1;
        Kl[base] = l0; Kl[base + 1] = l1;
    }
    __syncthreads();

    float C[2][8][4] = {};

    #pragma unroll
    for (int t3 = 0; t3 < 3; t3++) {
        const uint32_t* A = (t3 == 2) ? Ql : Qh;
        const uint32_t* B = (t3 == 1) ? Kl : Kh;
        #pragma unroll
        for (int ks = 0; ks < 4; ks++) {
            int kb = ks * 8;
            uint32_t a[2][4], bf[8][2];
            #pragma unroll
            for (int mt = 0; mt < 2; mt++) {
                int row = wi * 32 + mt * 16 + g;
                a[mt][0] = A[row * UPITCH + kb + c];
                a[mt][1] = A[(row + 8) * UPITCH + kb + c];
                a[mt][2] = A[row * UPITCH + kb + c + 4];
                a[mt][3] = A[(row + 8) * UPITCH + kb + c + 4];
            }
            #pragma unroll
            for (int nt = 0; nt < 8; nt++) {
                int jr = wj * 64 + nt * 8 + g;
                bf[nt][0] = B[jr * UPITCH + kb + c];
                bf[nt][1] = B[jr * UPITCH + kb + c + 4];
            }
            #pragma unroll
            for (int mt = 0; mt < 2; mt++)
                #pragma unroll
                for (int nt = 0; nt < 8; nt++)
                    mma_bf16(C[mt][nt], a[mt], bf[nt]);
        }
    }

    // exp, store E fp32, accumulate column partials
    float part[16];
    #pragma unroll
    for (int p = 0; p < 16; p++) part[p] = 0.f;

    #pragma unroll
    for (int mt = 0; mt < 2; mt++) {
        #pragma unroll
        for (int nt = 0; nt < 8; nt++) {
            float e0 = __expf(C[mt][nt][0]);
            float e1 = __expf(C[mt][nt][1]);
            float e2 = __expf(C[mt][nt][2]);
            float e3 = __expf(C[mt][nt][3]);
            int ig = i0 + wi * 32 + mt * 16 + g;
            int jg = j0 + wj * 64 + nt * 8 + 2 * c;
            *(float2*)(g_E + ((size_t)b * SS + ig) * SS + jg)     = make_float2(e0, e1);
            *(float2*)(g_E + ((size_t)b * SS + ig + 8) * SS + jg) = make_float2(e2, e3);
            part[nt * 2 + 0] += e0 + e2;
            part[nt * 2 + 1] += e1 + e3;
        }
    }
    #pragma unroll
    for (int p = 0; p < 16; p++) red[tid * 17 + p] = part[p];
    __syncthreads();

    if (tid < 128) {
        int t_wj = tid >> 6, jl = tid & 63;
        int nt = jl >> 3, cc = (jl & 7) >> 1, par = jl & 1;
        int p = nt * 2 + par;
        float s = 0.f;
        #pragma unroll
        for (int twi = 0; twi < 4; twi++)
            #pragma unroll
            for (int q = 0; q < 8; q++)
                s += red[((twi * 2 + t_wj) * 32 + q * 4 + cc) * 17 + p];
        g_Zpart[((size_t)(b * 16 + blockIdx.x)) * SS + j0 + tid] = s;
    }
}

// =====================================================================================
// Kernel 3/4: Z reduce ; Wvt[b][d][k] = tf32rna(V[k][d] / Z[k]).
// =====================================================================================
__global__ void zinv_kernel() {
    int t = blockIdx.x * 256 + threadIdx.x;
    int b = t >> 11, j = t & 2047;
    float s = 0.f;
    #pragma unroll
    for (int p = 0; p < 16; p++) s += g_Zpart[((size_t)(b * 16 + p)) * SS + j];
    g_Zinv[t] = 1.0f / s;
}

__global__ __launch_bounds__(256) void vscale_kernel() {
    __shared__ float vs[64][65];
    const int b = blockIdx.y, k0 = blockIdx.x * 64, t = threadIdx.x;
    for (int idx = t; idx < 1024; idx += 256) {
        int r = idx >> 4, c4 = (idx & 15) << 2;
        float zi = g_Zinv[b * SS + k0 + r];
        float4 v = *(const float4*)(g_V + ((size_t)(b * SS + k0 + r)) * DD + c4);
        vs[r][c4 + 0] = v.x * zi; vs[r][c4 + 1] = v.y * zi;
        vs[r][c4 + 2] = v.z * zi; vs[r][c4 + 3] = v.w * zi;
    }
    __syncthreads();
    for (int idx = t; idx < 1024; idx += 256) {
        int d = idx >> 4, c4 = (idx & 15) << 2;
        float4 o;
        o.x = tf32rna(vs[c4 + 0][d]);
        o.y = tf32rna(vs[c4 + 1][d]);
        o.z = tf32rna(vs[c4 + 2][d]);
        o.w = tf32rna(vs[c4 + 3][d]);
        *(float4*)(g_Wvt + ((size_t)(b * DD + d)) * SS + k0 + c4) = o;
    }
}

// =====================================================================================
// Kernel 5 (out): partial out = E[i, k-chunk] @ Wvt^T, SINGLE tf32 mma.sync.
// grid (16 i, 8 ksplit, 4 b), 256 threads (8 warps 4x2 over M=128, N=64).
// =====================================================================================
#define OU_SMEM (128 * PITCH * 4 + 64 * PITCH * 4)    // 34816 + 17408 = 52224

__global__ __launch_bounds__(256) void out_kernel() {
    extern __shared__ float sm[];
    float* Et = sm;                 // [128][68] tf32-rounded E
    float* Wt = sm + 128 * PITCH;   // [64][68]  pre-rounded Wvt

    const int tid = threadIdx.x, lane = tid & 31, warp = tid >> 5;
    const int wi = warp >> 1, wj = warp & 1;
    const int g = lane >> 2, c = lane & 3;
    const int b = blockIdx.z, i0 = blockIdx.x * 128, ks_id = blockIdx.y;

    float C[2][4][4] = {};

    for (int kc = 0; kc < 4; kc++) {
        const int k0 = ks_id * 256 + kc * 64;
        ldt_cvt(Et, g_E + ((size_t)b * SS + i0) * SS + k0, 128, SS);
        ldt(Wt, g_Wvt + (size_t)b * DD * SS + k0, 64, SS);
        __syncthreads();

        #pragma unroll
        for (int ks = 0; ks < 8; ks++) {
            const int kk = ks * 8;
            uint32_t a[2][4], bf[4][2];
            #pragma unroll
            for (int mt = 0; mt < 2; mt++) {
                int row = wi * 32 + mt * 16 + g;
                a[mt][0] = __float_as_uint(Et[row * PITCH + kk + c]);
                a[mt][1] = __float_as_uint(Et[(row + 8) * PITCH + kk + c]);
                a[mt][2] = __float_as_uint(Et[row * PITCH + kk + c + 4]);
                a[mt][3] = __float_as_uint(Et[(row + 8) * PITCH + kk + c + 4]);
            }
            #pragma unroll
            for (int nt = 0; nt < 4; nt++) {
                int dr = wj * 32 + nt * 8 + g;
                bf[nt][0] = __float_as_uint(Wt[dr * PITCH + kk + c]);
                bf[nt][1] = __float_as_uint(Wt[dr * PITCH + kk + c + 4]);
            }
            #pragma unroll
            for (int mt = 0; mt < 2; mt++)
                #pragma unroll
                for (int nt = 0; nt < 4; nt++)
                    mma168(C[mt][nt], a[mt], bf[nt]);
        }
        __syncthreads();
    }

    #pragma unroll
    for (int mt = 0; mt < 2; mt++) {
        #pragma unroll
        for (int nt = 0; nt < 4; nt++) {
            int ig = i0 + wi * 32 + mt * 16 + g;
            int dg = wj * 32 + nt * 8 + 2 * c;
            size_t base = ((size_t)((b * 8 + ks_id) * SS + ig)) * DD + dg;
            *(float2*)(g_Opart + base) = make_float2(C[mt][nt][0], C[mt][nt][1]);
            *(float2*)(g_Opart + base + 8 * DD) = make_float2(C[mt][nt][2], C[mt][nt][3]);
        }
    }
}

// =====================================================================================
// Kernel 6: reduce 8 k-split partials, write 16 tiled head copies.
// =====================================================================================
__global__ void finalize_kernel(float* __restrict__ out) {
    int gI = blockIdx.x * 256 + threadIdx.x;    // 0 .. BB*SS*16-1
    int c4 = (gI & 15) << 2;
    int i  = (gI >> 4) & 2047;
    int b  = gI >> 15;
    float4 s = make_float4(0.f, 0.f, 0.f, 0.f);
    #pragma unroll
    for (int sp = 0; sp < 8; sp++) {
        float4 p = *(const float4*)(g_Opart + ((size_t)((b * 8 + sp) * SS + i)) * DD + c4);
        s.x += p.x; s.y += p.y; s.z += p.z; s.w += p.w;
    }
    float* base = out + ((size_t)(b * SS + i)) * (HH * DD) + c4;
    #pragma unroll
    for (int h = 0; h < HH; h++) *(float4*)(base + h * DD) = s;
}

// =====================================================================================
extern "C" void kernel_launch(void* const* d_in, const int* in_sizes, int n_in,
                              void* d_out, int out_size) {
    const float* x  = (const float*)d_in[0];
    const float* Wq = (const float*)d_in[1];
    const float* Wk = (const float*)d_in[2];
    const float* Wv = (const float*)d_in[3];
    float* out = (float*)d_out;

    cudaFuncSetAttribute(score_kernel, cudaFuncAttributeMaxDynamicSharedMemorySize, SC_SMEM);
    cudaFuncSetAttribute(out_kernel,   cudaFuncAttributeMaxDynamicSharedMemorySize, OU_SMEM);

    wsplit_kernel<<<192, 256>>>(Wq, Wk, Wv);
    projmma_kernel<<<dim3(128, 3), 128>>>(x);
    score_kernel<<<dim3(16, 16, BB), 256, SC_SMEM>>>();
    zinv_kernel<<<(BB * SS) / 256, 256>>>();
    vscale_kernel<<<dim3(SS / 64, BB), 256>>>();
    out_kernel<<<dim3(16, 8, BB), 256, OU_SMEM>>>();
    finalize_kernel<<<(BB * SS * HH) / 256, 256>>>(out);
}